// round 11
// baseline (speedup 1.0000x reference)
#include <cuda_runtime.h>
#include <cuda.h>
#include <cstdint>

// ============================================================================
// out[16384,2048] = relu( (x / (||x||_2 + 1e-4)) @ W^T + b )
//
// Persistent 2-CTA (cta_group::2) tcgen05 tf32 GEMM, M=256 x N=256 cluster
// tiles, A split M/2 / B split N/2 per CTA (no duplicated loads).
// NEW (R10): row-norm pre-kernel DELETED — epilogue warps compute their own
// 32 rows' inv-norms from gmem during the mainloop (hidden behind MMA),
// removing a 134MB pre-pass + extra launch (~25us of the 28us non-GEMM time).
//   rank0 warp 5: cg2 MMA issue   | rank1 warp 5: full-barrier relay to leader
//   warp 4 (both): TMA producer   | warps 0-3 (both): norm + epilogue
// ============================================================================

#if defined(__CUDA_ARCH_FEAT_SM103_ALL) || defined(__CUDA_ARCH_FEAT_SM100_ALL) || \
    defined(__CUDA_ARCH_FEAT_SM101_ALL)
#define HAS_TCGEN05 1
#else
#define HAS_TCGEN05 0
#endif

#define B_ROWS 16384
#define K_DIM  2048
#define N_DIM  2048

#define BM 128                // per-CTA M rows (cluster M = 256)
#define BNC 256               // cluster N width (128 B-rows per CTA)
#define BK 32                 // 32 f32 = 128B rows -> SW128
#define STAGES 6
#define KT (K_DIM / BK)       // 64 k-iterations per tile
#define THREADS 192
#define GRID_P 148
#define NCLUST (GRID_P / 2)   // 74 clusters
#define NSUPC ((B_ROWS / 256) * (N_DIM / BNC))   // 64*8 = 512 cluster-tiles

// dynamic smem layout (per CTA)
#define OFF_FULL(s)  ((s) * 8)
#define OFF_EMPTY(s) (64 + (s) * 8)
#define OFF_ACCF(b)  (128 + (b) * 8)
#define OFF_ACCE(b)  (144 + (b) * 8)
#define OFF_TMEM     160
#define OFF_NORM     256      // fallback-path norm table (128 floats)
#define OFF_DATA     1024
#define A_BYTES      16384    // 128 rows x 128B
#define STAGE_BYTES  32768
#define SMEM_TOTAL   (OFF_DATA + STAGES * STAGE_BYTES)   // 197632 (known-safe)

// tf32 cg2 idesc: D=f32, A=tf32, B=tf32, N=256 (32<<17), M=256 (16<<24)
#define IDESC_CG2 0x10400910u

// ---------------------------------------------------------------- PTX helpers
__device__ __forceinline__ uint32_t smem_u32(const void* p) {
    uint32_t a;
    asm("{ .reg .u64 t; cvta.to.shared.u64 t, %1; cvt.u32.u64 %0, t; }"
        : "=r"(a) : "l"(p));
    return a;
}

__device__ __forceinline__ uint32_t cluster_rank() {
    uint32_t r;
    asm("mov.u32 %0, %%cluster_ctarank;" : "=r"(r));
    return r;
}

#define CLUSTER_SYNC() do {                                          \
    asm volatile("barrier.cluster.arrive.aligned;" ::: "memory");    \
    asm volatile("barrier.cluster.wait.aligned;" ::: "memory");      \
} while (0)

#define MBARRIER_INIT(addr, cnt) \
    asm volatile("mbarrier.init.shared.b64 [%0], %1;" :: "r"(addr), "r"(cnt) : "memory")

#define MBARRIER_EXPECT_TX(addr, bytes) \
    asm volatile("mbarrier.arrive.expect_tx.shared.b64 _, [%0], %1;" \
                 :: "r"(addr), "r"(bytes) : "memory")

#define MBARRIER_ARRIVE(addr) \
    asm volatile("mbarrier.arrive.shared.b64 _, [%0];" :: "r"(addr) : "memory")

// arrive on the mbarrier at the same smem offset in cluster rank 0
#define MBARRIER_ARRIVE_RANK0(addr) do {                                   \
    uint32_t _zero = 0;                                                    \
    asm volatile(                                                          \
        "{\n\t"                                                            \
        ".reg .b32 ra;\n\t"                                                \
        "mapa.shared::cluster.u32 ra, %0, %1;\n\t"                         \
        "mbarrier.arrive.shared::cluster.b64 _, [ra];\n\t"                 \
        "}"                                                                \
        :: "r"((uint32_t)(addr)), "r"(_zero) : "memory");                  \
} while (0)

#define MBARRIER_WAIT_PARITY(addr, parity) do {                                   \
    asm volatile(                                                                 \
        "{\n\t"                                                                   \
        ".reg .pred P1;\n\t"                                                      \
        "WAIT_LOOP_%=:\n\t"                                                       \
        "mbarrier.try_wait.parity.acquire.cta.shared::cta.b64 P1, [%0], %1, 0x989680;\n\t" \
        "@P1 bra.uni WAIT_DONE_%=;\n\t"                                           \
        "bra.uni WAIT_LOOP_%=;\n\t"                                               \
        "WAIT_DONE_%=:\n\t"                                                       \
        "}"                                                                       \
        :: "r"((uint32_t)(addr)), "r"((uint32_t)(parity)) : "memory");            \
} while (0)

#define TMA_LOAD_2D(smem_addr, map_ptr, cx, cy, mbar)                                      \
    asm volatile(                                                                          \
        "cp.async.bulk.tensor.2d.shared::cta.global.tile.mbarrier::complete_tx::bytes "    \
        "[%0], [%1, {%2, %3}], [%4];"                                                      \
        :: "r"(smem_addr), "l"(map_ptr), "r"(cx), "r"(cy), "r"(mbar) : "memory")

// fallback path primitives (base features)
#define LDSM_X4(r, addr)                                                        \
    asm volatile("ldmatrix.sync.aligned.m8n8.x4.shared.b16 {%0,%1,%2,%3}, [%4];"\
        : "=r"((r)[0]), "=r"((r)[1]), "=r"((r)[2]), "=r"((r)[3]) : "r"(addr))

#define MMA_TF32(c, a, b0_, b1_)                                                \
    asm volatile("mma.sync.aligned.m16n8k8.row.col.f32.tf32.tf32.f32 "          \
        "{%0,%1,%2,%3}, {%4,%5,%6,%7}, {%8,%9}, {%0,%1,%2,%3};"                 \
        : "+f"((c)[0]), "+f"((c)[1]), "+f"((c)[2]), "+f"((c)[3])                \
        : "r"((a)[0]), "r"((a)[1]), "r"((a)[2]), "r"((a)[3]),                   \
          "r"(b0_), "r"(b1_))

#if HAS_TCGEN05
#define TCGEN05_ALLOC_CG2(smem_addr, ncols) \
    asm volatile("tcgen05.alloc.cta_group::2.sync.aligned.shared::cta.b32 [%0], %1;" \
                 :: "r"(smem_addr), "r"(ncols) : "memory")
#define TCGEN05_RELINQ_CG2() \
    asm volatile("tcgen05.relinquish_alloc_permit.cta_group::2.sync.aligned;")
#define TCGEN05_DEALLOC_CG2(tmem, ncols) \
    asm volatile("tcgen05.dealloc.cta_group::2.sync.aligned.b32 %0, %1;" :: "r"(tmem), "r"(ncols))
#define TCGEN05_COMMIT_MC_CG2(mbar, mask) \
    asm volatile("tcgen05.commit.cta_group::2.mbarrier::arrive::one.shared::cluster" \
                 ".multicast::cluster.b64 [%0], %1;" \
                 :: "r"(mbar), "h"((uint16_t)(mask)) : "memory")
#define TCGEN05_FENCE_AFTER() \
    asm volatile("tcgen05.fence::after_thread_sync;" ::: "memory")
#define TCGEN05_FENCE_BEFORE() \
    asm volatile("tcgen05.fence::before_thread_sync;" ::: "memory")
#define TCGEN05_WAIT_LD() \
    asm volatile("tcgen05.wait::ld.sync.aligned;" ::: "memory")

__device__ __forceinline__ uint64_t make_desc_sw128(uint32_t base) {
    const uint64_t D = (uint64_t(2) << 61) | (uint64_t(1) << 46) |
                       (uint64_t(64) << 32) | (uint64_t(1) << 16);
    return D | ((uint64_t)(base >> 4) & 0x3FFF);
}

__device__ __forceinline__ void mma_tf32_ss_cg2(uint32_t d_tmem, uint64_t a_desc,
                                                uint64_t b_desc, uint32_t idesc,
                                                uint32_t enable_d) {
    asm volatile(
        "{\n\t"
        ".reg .pred p;\n\t"
        "setp.ne.u32 p, %5, 0;\n\t"
        "tcgen05.mma.cta_group::2.kind::tf32 [%0], %1, %2, %3, "
        "{%4, %4, %4, %4, %4, %4, %4, %4}, p;\n\t"
        "}"
        :: "r"(d_tmem), "l"(a_desc), "l"(b_desc), "r"(idesc), "r"(0u),
           "r"(enable_d)
        : "memory");
}

#define LDTM_X32(r, addr)                                                       \
    asm volatile(                                                               \
        "tcgen05.ld.sync.aligned.32x32b.x32.b32 "                               \
        "{%0, %1, %2, %3, %4, %5, %6, %7, "                                     \
        " %8, %9, %10, %11, %12, %13, %14, %15, "                               \
        " %16, %17, %18, %19, %20, %21, %22, %23, "                             \
        " %24, %25, %26, %27, %28, %29, %30, %31}, [%32];"                      \
        : "=r"((r)[0]),  "=r"((r)[1]),  "=r"((r)[2]),  "=r"((r)[3]),            \
          "=r"((r)[4]),  "=r"((r)[5]),  "=r"((r)[6]),  "=r"((r)[7]),            \
          "=r"((r)[8]),  "=r"((r)[9]),  "=r"((r)[10]), "=r"((r)[11]),           \
          "=r"((r)[12]), "=r"((r)[13]), "=r"((r)[14]), "=r"((r)[15]),           \
          "=r"((r)[16]), "=r"((r)[17]), "=r"((r)[18]), "=r"((r)[19]),           \
          "=r"((r)[20]), "=r"((r)[21]), "=r"((r)[22]), "=r"((r)[23]),           \
          "=r"((r)[24]), "=r"((r)[25]), "=r"((r)[26]), "=r"((r)[27]),           \
          "=r"((r)[28]), "=r"((r)[29]), "=r"((r)[30]), "=r"((r)[31])            \
        : "r"(addr))
#endif  // HAS_TCGEN05

// Warp-cooperative inv-norm of one x row: 32 lanes each load 16 float4
// (coalesced 512B per step), reduce via shfl. All lanes return the value.
__device__ __forceinline__ float warp_row_invnorm(const float* __restrict__ x,
                                                  int row, int lane) {
    const float4* xr = (const float4*)(x + (size_t)row * K_DIM);
    float ss = 0.f;
#pragma unroll
    for (int j = 0; j < 16; j++) {
        float4 v = __ldg(&xr[lane + j * 32]);
        ss += v.x * v.x + v.y * v.y + v.z * v.z + v.w * v.w;
    }
#pragma unroll
    for (int o = 16; o > 0; o >>= 1) ss += __shfl_xor_sync(0xffffffffu, ss, o);
    return 1.f / (sqrtf(ss) + 1e-4f);
}

// ---------------------------------------------------------------- GEMM kernel
__global__ __launch_bounds__(THREADS, 1) __cluster_dims__(2, 1, 1)
void ff_gemm_kernel(
    const __grid_constant__ CUtensorMap tma_a,
    const __grid_constant__ CUtensorMap tma_b,
    const float* __restrict__ xg,
    const float* __restrict__ bias,
    float* __restrict__ out)
{
    extern __shared__ char smem[];
    uint32_t sb = smem_u32(smem);
    int tid = threadIdx.x;
    int wid = tid >> 5;
    int lane = tid & 31;

#if HAS_TCGEN05
    // ============= persistent cg2 path: 256x256 cluster tiles ==============
    uint32_t rank = cluster_rank();
    int cid = blockIdx.x >> 1;

    if (tid == 0) {
#pragma unroll
        for (int s = 0; s < STAGES; s++) {
            // leader full: local expect_tx arrive + relay arrive from rank1
            MBARRIER_INIT(sb + OFF_FULL(s), rank == 0 ? 2 : 1);
            MBARRIER_INIT(sb + OFF_EMPTY(s), 1);   // cg2 commit multicast
        }
#pragma unroll
        for (int b2 = 0; b2 < 2; b2++) {
            MBARRIER_INIT(sb + OFF_ACCF(b2), 1);   // cg2 commit multicast
            MBARRIER_INIT(sb + OFF_ACCE(b2), 8);   // 4 epi warps x 2 CTAs (leader)
        }
    }
    if (wid == 5) {
        TCGEN05_ALLOC_CG2(sb + OFF_TMEM, 512);     // 2 x 256-col acc buffers
    }
    __syncthreads();
    CLUSTER_SYNC();   // barriers + TMEM visible before any cluster-scope op

    uint32_t tmem;
    asm volatile("ld.shared.b32 %0, [%1];" : "=r"(tmem) : "r"(sb + OFF_TMEM));

    if (wid == 4) {
        // ---- TMA producer (both ranks): distinct A M-half + B N-half ----
        if (lane == 0) {
            int s = 0, pe = 1;
            for (int t = cid; t < NSUPC; t += NCLUST) {
                int n0 = (t & 7) * BNC + (int)rank * 128;     // B rows (N-half)
                int m0 = (t >> 3) * 256 + (int)rank * 128;    // A rows (M-half)
                for (int k = 0; k < KT; k++) {
                    MBARRIER_WAIT_PARITY(sb + OFF_EMPTY(s), pe);
                    uint32_t st = sb + OFF_DATA + s * STAGE_BYTES;
                    MBARRIER_EXPECT_TX(sb + OFF_FULL(s), STAGE_BYTES);
                    TMA_LOAD_2D(st,           &tma_a, k * BK, m0, sb + OFF_FULL(s));
                    TMA_LOAD_2D(st + A_BYTES, &tma_b, k * BK, n0, sb + OFF_FULL(s));
                    if (++s == STAGES) { s = 0; pe ^= 1; }
                }
            }
        }
    } else if (wid == 5) {
        if (rank == 0) {
            // ---- leader MMA warp: cg2 M=256 N=256 ----
            TCGEN05_FENCE_AFTER();
            if (lane == 0) {
                int s = 0, pf = 0;
                int pae0 = 1, pae1 = 1;
                int ti = 0;
                for (int t = cid; t < NSUPC; t += NCLUST, ti++) {
                    int buf = ti & 1;
                    if (buf) { MBARRIER_WAIT_PARITY(sb + OFF_ACCE(1), pae1); pae1 ^= 1; }
                    else     { MBARRIER_WAIT_PARITY(sb + OFF_ACCE(0), pae0); pae0 ^= 1; }
                    uint32_t dacc = tmem + buf * 256;
                    for (int k = 0; k < KT; k++) {
                        MBARRIER_WAIT_PARITY(sb + OFF_FULL(s), pf);
                        uint32_t st = sb + OFF_DATA + s * STAGE_BYTES;
                        uint64_t ad = make_desc_sw128(st);
                        uint64_t bd = make_desc_sw128(st + A_BYTES);
#pragma unroll
                        for (int sub = 0; sub < 4; sub++) {
                            mma_tf32_ss_cg2(dacc, ad + sub * 2, bd + sub * 2,
                                            IDESC_CG2, (uint32_t)(k | sub));
                        }
                        // stage reusable in BOTH CTAs when these MMAs complete
                        TCGEN05_COMMIT_MC_CG2(sb + OFF_EMPTY(s), 0x3);
                        if (++s == STAGES) { s = 0; pf ^= 1; }
                    }
                    TCGEN05_COMMIT_MC_CG2(sb + OFF_ACCF(buf), 0x3);
                }
            }
        } else {
            // ---- rank1 relay: forward local TMA completions to leader ----
            if (lane == 0) {
                int s = 0, pr = 0;
                for (int t = cid; t < NSUPC; t += NCLUST) {
                    for (int k = 0; k < KT; k++) {
                        MBARRIER_WAIT_PARITY(sb + OFF_FULL(s), pr);
                        MBARRIER_ARRIVE_RANK0(sb + OFF_FULL(s));
                        if (++s == STAGES) { s = 0; pr ^= 1; }
                    }
                }
            }
        }
    } else {
        // ---- epilogue warps 0-3 (both ranks): fused norm + drain ----
        int pfa0 = 0, pfa1 = 0;
        int ti = 0;
        for (int t = cid; t < NSUPC; t += NCLUST, ti++) {
            int buf = ti & 1;
            int n0 = (t & 7) * BNC;
            int m0 = (t >> 3) * 256 + (int)rank * 128;
            int m = m0 + wid * 32 + lane;

            // fused row-norm: overlaps with this tile's MMA mainloop.
            // lane r keeps inv-norm of row (base + r).
            float inv = 0.f;
            {
                int rb = m0 + wid * 32;
#pragma unroll 4
                for (int r = 0; r < 32; r++) {
                    float iv = warp_row_invnorm(xg, rb + r, lane);
                    if (lane == r) inv = iv;
                }
            }

            if (buf) { MBARRIER_WAIT_PARITY(sb + OFF_ACCF(1), pfa1); pfa1 ^= 1; }
            else     { MBARRIER_WAIT_PARITY(sb + OFF_ACCF(0), pfa0); pfa0 ^= 1; }
            TCGEN05_FENCE_AFTER();

            float* orow = out + (size_t)m * N_DIM + n0;
            uint32_t tb = tmem + buf * 256;
#pragma unroll
            for (int cb = 0; cb < BNC; cb += 32) {
                uint32_t r[32];
                LDTM_X32(r, tb + cb);
                TCGEN05_WAIT_LD();
#pragma unroll
                for (int i = 0; i < 32; i += 4) {
                    float4 bv = __ldg((const float4*)&bias[n0 + cb + i]);
                    float4 v;
                    v.x = fmaxf(fmaf(__uint_as_float(r[i + 0]), inv, bv.x), 0.f);
                    v.y = fmaxf(fmaf(__uint_as_float(r[i + 1]), inv, bv.y), 0.f);
                    v.z = fmaxf(fmaf(__uint_as_float(r[i + 2]), inv, bv.z), 0.f);
                    v.w = fmaxf(fmaf(__uint_as_float(r[i + 3]), inv, bv.w), 0.f);
                    *(float4*)(orow + cb + i) = v;
                }
            }
            TCGEN05_FENCE_BEFORE();
            __syncwarp();
            if (lane == 0) MBARRIER_ARRIVE_RANK0(sb + OFF_ACCE(buf));
        }
    }
    __syncthreads();
    CLUSTER_SYNC();   // all TMEM reads done in both CTAs before dealloc
    if (wid == 5) {
        TCGEN05_RELINQ_CG2();
        TCGEN05_DEALLOC_CG2(tmem, 512);
    }
    CLUSTER_SYNC();   // no CTA exits while peer ops may target its smem

#else
    // ============ fallback (plain sm_103): persistent mma.sync path ========
#define NTILE_FB ((B_ROWS / BM) * (N_DIM / 128))   // 2048
    int bid = blockIdx.x;
    if (tid == 0) {
#pragma unroll
        for (int s = 0; s < STAGES; s++) {
            MBARRIER_INIT(sb + OFF_FULL(s), 1);
            MBARRIER_INIT(sb + OFF_EMPTY(s), 4);
        }
    }
    __syncthreads();

    if (wid == 4) {
        if (lane == 0) {
            int s = 0, pe = 1;
            for (int t = bid; t < NTILE_FB; t += GRID_P) {
                int n0 = (t & 15) * 128;
                int m0 = (t >> 4) * BM;
                for (int k = 0; k < KT; k++) {
                    MBARRIER_WAIT_PARITY(sb + OFF_EMPTY(s), pe);
                    uint32_t st = sb + OFF_DATA + s * STAGE_BYTES;
                    MBARRIER_EXPECT_TX(sb + OFF_FULL(s), 32768);
                    TMA_LOAD_2D(st,           &tma_a, k * BK, m0, sb + OFF_FULL(s));
                    TMA_LOAD_2D(st + A_BYTES, &tma_b, k * BK, n0, sb + OFF_FULL(s));
                    if (++s == STAGES) { s = 0; pe ^= 1; }
                }
            }
        }
    } else if (wid < 4) {
        int wm = wid >> 1, wn = wid & 1;
        const int xorpat = (lane & 7) << 4;
        const int a_row  = wm * 64 + (lane & 15);
        const int a_colb = (lane >> 4) * 16;
        const int b_row  = wn * 64 + (lane & 7) + ((lane >> 4) * 8);
        const int b_colb = ((lane >> 3) & 1) * 16;
        float* ninv = (float*)(smem + OFF_NORM);   // 128 floats per tile

        int s = 0, pf = 0;
        for (int t = bid; t < NTILE_FB; t += GRID_P) {
            int n0 = (t & 15) * 128;
            int m0 = (t >> 4) * BM;

            // inline norm for this tile's 128 rows (warp w: rows w*32..w*32+31)
            {
                int rb = m0 + wid * 32;
                for (int r = 0; r < 32; r++) {
                    float iv = warp_row_invnorm(xg, rb + r, lane);
                    if (lane == 0) ninv[wid * 32 + r] = iv;
                }
            }
            asm volatile("bar.sync 1, 128;" ::: "memory");   // 4 consumer warps

            float c[4][8][4];
#pragma unroll
            for (int a1 = 0; a1 < 4; a1++)
#pragma unroll
                for (int a2 = 0; a2 < 8; a2++)
#pragma unroll
                    for (int a3 = 0; a3 < 4; a3++) c[a1][a2][a3] = 0.f;

            for (int k = 0; k < KT; k++) {
                MBARRIER_WAIT_PARITY(sb + OFF_FULL(s), pf);
                uint32_t sa  = sb + OFF_DATA + s * STAGE_BYTES;
                uint32_t sbm = sa + A_BYTES;
#pragma unroll
                for (int q = 0; q < 4; q++) {
                    uint32_t a[4][4], bf[4][4];
#pragma unroll
                    for (int mt = 0; mt < 4; mt++) {
                        uint32_t addr = sa + (uint32_t)((a_row + mt * 16) * 128 +
                                         ((q * 32 + a_colb) ^ xorpat));
                        LDSM_X4(a[mt], addr);
                    }
#pragma unroll
                    for (int p = 0; p < 4; p++) {
                        uint32_t addr = sbm + (uint32_t)((b_row + p * 16) * 128 +
                                         ((q * 32 + b_colb) ^ xorpat));
                        LDSM_X4(bf[p], addr);
                    }
#pragma unroll
                    for (int mt = 0; mt < 4; mt++)
#pragma unroll
                        for (int nt = 0; nt < 8; nt++) {
                            const uint32_t* bb = &bf[nt >> 1][(nt & 1) * 2];
                            MMA_TF32(c[mt][nt], a[mt], bb[0], bb[1]);
                        }
                }
                __syncwarp();
                if (lane == 0) MBARRIER_ARRIVE(sb + OFF_EMPTY(s));
                if (++s == STAGES) { s = 0; pf ^= 1; }
            }

            int g = lane >> 2, tt = lane & 3;
#pragma unroll
            for (int mt = 0; mt < 4; mt++) {
                int r0 = m0 + wm * 64 + mt * 16 + g;
                float inv0 = ninv[r0 - m0];
                float inv1 = ninv[r0 - m0 + 8];
                float* p0 = out + (size_t)r0 * N_DIM + n0;
                float* p1 = out + (size_t)(r0 + 8) * N_DIM + n0;
#pragma unroll
                for (int nt = 0; nt < 8; nt++) {
                    int cl = wn * 64 + nt * 8 + 2 * tt;
                    float b0 = __ldg(&bias[n0 + cl]), b1 = __ldg(&bias[n0 + cl + 1]);
                    float2 v0, v1;
                    v0.x = fmaxf(fmaf(c[mt][nt][0], inv0, b0), 0.f);
                    v0.y = fmaxf(fmaf(c[mt][nt][1], inv0, b1), 0.f);
                    v1.x = fmaxf(fmaf(c[mt][nt][2], inv1, b0), 0.f);
                    v1.y = fmaxf(fmaf(c[mt][nt][3], inv1, b1), 0.f);
                    *(float2*)(p0 + cl) = v0;
                    *(float2*)(p1 + cl) = v1;
                }
            }
            asm volatile("bar.sync 1, 128;" ::: "memory");   // protect ninv reuse
        }
    }
#endif
}

// ---------------------------------------------------------------- host side
typedef CUresult (*PFN_encodeTiled)(
    CUtensorMap*, CUtensorMapDataType, cuuint32_t, void*,
    const cuuint64_t*, const cuuint64_t*, const cuuint32_t*, const cuuint32_t*,
    CUtensorMapInterleave, CUtensorMapSwizzle, CUtensorMapL2promotion,
    CUtensorMapFloatOOBfill);

static PFN_encodeTiled get_encoder() {
    void* p = nullptr;
    cudaDriverEntryPointQueryResult st;
    cudaGetDriverEntryPointByVersion("cuTensorMapEncodeTiled", &p, 12000,
                                     cudaEnableDefault, &st);
    return (PFN_encodeTiled)p;
}

static void make_map(PFN_encodeTiled enc, CUtensorMap* map, const void* base,
                     uint64_t rows) {
    cuuint64_t dims[2]    = {(cuuint64_t)K_DIM, (cuuint64_t)rows};
    cuuint64_t strides[1] = {(cuuint64_t)K_DIM * sizeof(float)};
    cuuint32_t box[2]     = {(cuuint32_t)BK, (cuuint32_t)BM};
    cuuint32_t es[2]      = {1, 1};
    enc(map, CU_TENSOR_MAP_DATA_TYPE_FLOAT32, 2, (void*)base,
        dims, strides, box, es,
        CU_TENSOR_MAP_INTERLEAVE_NONE, CU_TENSOR_MAP_SWIZZLE_128B,
        CU_TENSOR_MAP_L2_PROMOTION_L2_128B, CU_TENSOR_MAP_FLOAT_OOB_FILL_NONE);
}

extern "C" void kernel_launch(void* const* d_in, const int* in_sizes, int n_in,
                              void* d_out, int out_size) {
    const float* x = (const float*)d_in[0];
    const float* W = (const float*)d_in[1];
    const float* b = (const float*)d_in[2];
    float* out = (float*)d_out;

    cudaFuncSetAttribute(ff_gemm_kernel,
                         cudaFuncAttributeMaxDynamicSharedMemorySize, SMEM_TOTAL);

    PFN_encodeTiled enc = get_encoder();
    CUtensorMap mapA, mapB;
    make_map(enc, &mapA, x, B_ROWS);
    make_map(enc, &mapB, W, N_DIM);

    ff_gemm_kernel<<<GRID_P, THREADS, SMEM_TOTAL>>>(mapA, mapB, x, b, out);
}

// round 14
// speedup vs baseline: 1.4204x; 1.4204x over previous
#include <cuda_runtime.h>
#include <cuda.h>
#include <cstdint>

// ============================================================================
// out[16384,2048] = relu( (x / (||x||_2 + 1e-4)) @ W^T + b )
//
// Persistent 2-CTA (cta_group::2) tcgen05 tf32 GEMM, M=256 x N=256 cluster
// tiles, A split M/2 / B split N/2 per CTA  (R9 pipeline, unchanged: it
// passed at 150.3us GEMM / 85.4% tensor; the R12/R13 smem-norm ring variant
// is abandoned after two container failures).
// R14: norm pre-kernel deleted. Epilogue warps compute each row's inv-norm
// EXACTLY ONCE chip-wide (CTA b owns rows 111*b..) from gmem during the
// first tile's mainloop (a window where they previously idled), then cross a
// one-shot grid barrier (148 CTAs all wave-1 resident; epoch+counter
// protocol self-resets for CUDA-graph replay). Epilogues read g_inv_norm.
//   rank0 warp 5: cg2 MMA issue   | rank1 warp 5: full-barrier relay to leader
//   warp 4 (both): TMA producer   | warps 0-3 (both): norm-once + epilogue
// ============================================================================

#if defined(__CUDA_ARCH_FEAT_SM103_ALL) || defined(__CUDA_ARCH_FEAT_SM100_ALL) || \
    defined(__CUDA_ARCH_FEAT_SM101_ALL)
#define HAS_TCGEN05 1
#else
#define HAS_TCGEN05 0
#endif

#define B_ROWS 16384
#define K_DIM  2048
#define N_DIM  2048

#define BM 128                // per-CTA M rows (cluster M = 256)
#define BNC 256               // cluster N width (128 B-rows per CTA)
#define BK 32                 // 32 f32 = 128B rows -> SW128
#define STAGES 6
#define KT (K_DIM / BK)       // 64 k-iterations per tile
#define THREADS 192
#define GRID_P 148
#define NCLUST (GRID_P / 2)   // 74 clusters
#define NSUPC ((B_ROWS / 256) * (N_DIM / BNC))   // 64*8 = 512 cluster-tiles
#define ROWS_PER_CTA 111      // 148*111 = 16428 >= 16384

// dynamic smem layout (per CTA)
#define OFF_FULL(s)  ((s) * 8)
#define OFF_EMPTY(s) (64 + (s) * 8)
#define OFF_ACCF(b)  (128 + (b) * 8)
#define OFF_ACCE(b)  (144 + (b) * 8)
#define OFF_TMEM     160
#define OFF_NORM     256      // fallback-path norm table (128 floats)
#define OFF_DATA     1024
#define A_BYTES      16384    // 128 rows x 128B
#define STAGE_BYTES  32768
#define SMEM_TOTAL   (OFF_DATA + STAGES * STAGE_BYTES)   // 197632 (known-safe)

// tf32 cg2 idesc: D=f32, A=tf32, B=tf32, N=256 (32<<17), M=256 (16<<24)
#define IDESC_CG2 0x10400910u

__device__ float    g_inv_norm[B_ROWS];
__device__ unsigned g_cnt   = 0;   // returns to 0 every launch (last arriver)
__device__ unsigned g_epoch = 0;   // monotonic release epoch (wrap-safe)

// ---------------------------------------------------------------- PTX helpers
__device__ __forceinline__ uint32_t smem_u32(const void* p) {
    uint32_t a;
    asm("{ .reg .u64 t; cvta.to.shared.u64 t, %1; cvt.u32.u64 %0, t; }"
        : "=r"(a) : "l"(p));
    return a;
}

__device__ __forceinline__ uint32_t cluster_rank() {
    uint32_t r;
    asm("mov.u32 %0, %%cluster_ctarank;" : "=r"(r));
    return r;
}

__device__ __forceinline__ unsigned ld_acquire_gpu(const unsigned* p) {
    unsigned v;
    asm volatile("ld.acquire.gpu.u32 %0, [%1];" : "=r"(v) : "l"(p) : "memory");
    return v;
}

#define CLUSTER_SYNC() do {                                          \
    asm volatile("barrier.cluster.arrive.aligned;" ::: "memory");    \
    asm volatile("barrier.cluster.wait.aligned;" ::: "memory");      \
} while (0)

#define MBARRIER_INIT(addr, cnt) \
    asm volatile("mbarrier.init.shared.b64 [%0], %1;" :: "r"(addr), "r"(cnt) : "memory")

#define MBARRIER_EXPECT_TX(addr, bytes) \
    asm volatile("mbarrier.arrive.expect_tx.shared.b64 _, [%0], %1;" \
                 :: "r"(addr), "r"(bytes) : "memory")

#define MBARRIER_ARRIVE(addr) \
    asm volatile("mbarrier.arrive.shared.b64 _, [%0];" :: "r"(addr) : "memory")

// arrive on the mbarrier at the same smem offset in cluster rank 0
#define MBARRIER_ARRIVE_RANK0(addr) do {                                   \
    uint32_t _zero = 0;                                                    \
    asm volatile(                                                          \
        "{\n\t"                                                            \
        ".reg .b32 ra;\n\t"                                                \
        "mapa.shared::cluster.u32 ra, %0, %1;\n\t"                         \
        "mbarrier.arrive.shared::cluster.b64 _, [ra];\n\t"                 \
        "}"                                                                \
        :: "r"((uint32_t)(addr)), "r"(_zero) : "memory");                  \
} while (0)

#define MBARRIER_WAIT_PARITY(addr, parity) do {                                   \
    asm volatile(                                                                 \
        "{\n\t"                                                                   \
        ".reg .pred P1;\n\t"                                                      \
        "WAIT_LOOP_%=:\n\t"                                                       \
        "mbarrier.try_wait.parity.acquire.cta.shared::cta.b64 P1, [%0], %1, 0x989680;\n\t" \
        "@P1 bra.uni WAIT_DONE_%=;\n\t"                                           \
        "bra.uni WAIT_LOOP_%=;\n\t"                                               \
        "WAIT_DONE_%=:\n\t"                                                       \
        "}"                                                                       \
        :: "r"((uint32_t)(addr)), "r"((uint32_t)(parity)) : "memory");            \
} while (0)

#define TMA_LOAD_2D(smem_addr, map_ptr, cx, cy, mbar)                                      \
    asm volatile(                                                                          \
        "cp.async.bulk.tensor.2d.shared::cta.global.tile.mbarrier::complete_tx::bytes "    \
        "[%0], [%1, {%2, %3}], [%4];"                                                      \
        :: "r"(smem_addr), "l"(map_ptr), "r"(cx), "r"(cy), "r"(mbar) : "memory")

// fallback path primitives (base features)
#define LDSM_X4(r, addr)                                                        \
    asm volatile("ldmatrix.sync.aligned.m8n8.x4.shared.b16 {%0,%1,%2,%3}, [%4];"\
        : "=r"((r)[0]), "=r"((r)[1]), "=r"((r)[2]), "=r"((r)[3]) : "r"(addr))

#define MMA_TF32(c, a, b0_, b1_)                                                \
    asm volatile("mma.sync.aligned.m16n8k8.row.col.f32.tf32.tf32.f32 "          \
        "{%0,%1,%2,%3}, {%4,%5,%6,%7}, {%8,%9}, {%0,%1,%2,%3};"                 \
        : "+f"((c)[0]), "+f"((c)[1]), "+f"((c)[2]), "+f"((c)[3])                \
        : "r"((a)[0]), "r"((a)[1]), "r"((a)[2]), "r"((a)[3]),                   \
          "r"(b0_), "r"(b1_))

#if HAS_TCGEN05
#define TCGEN05_ALLOC_CG2(smem_addr, ncols) \
    asm volatile("tcgen05.alloc.cta_group::2.sync.aligned.shared::cta.b32 [%0], %1;" \
                 :: "r"(smem_addr), "r"(ncols) : "memory")
#define TCGEN05_RELINQ_CG2() \
    asm volatile("tcgen05.relinquish_alloc_permit.cta_group::2.sync.aligned;")
#define TCGEN05_DEALLOC_CG2(tmem, ncols) \
    asm volatile("tcgen05.dealloc.cta_group::2.sync.aligned.b32 %0, %1;" :: "r"(tmem), "r"(ncols))
#define TCGEN05_COMMIT_MC_CG2(mbar, mask) \
    asm volatile("tcgen05.commit.cta_group::2.mbarrier::arrive::one.shared::cluster" \
                 ".multicast::cluster.b64 [%0], %1;" \
                 :: "r"(mbar), "h"((uint16_t)(mask)) : "memory")
#define TCGEN05_FENCE_AFTER() \
    asm volatile("tcgen05.fence::after_thread_sync;" ::: "memory")
#define TCGEN05_FENCE_BEFORE() \
    asm volatile("tcgen05.fence::before_thread_sync;" ::: "memory")
#define TCGEN05_WAIT_LD() \
    asm volatile("tcgen05.wait::ld.sync.aligned;" ::: "memory")

__device__ __forceinline__ uint64_t make_desc_sw128(uint32_t base) {
    const uint64_t D = (uint64_t(2) << 61) | (uint64_t(1) << 46) |
                       (uint64_t(64) << 32) | (uint64_t(1) << 16);
    return D | ((uint64_t)(base >> 4) & 0x3FFF);
}

__device__ __forceinline__ void mma_tf32_ss_cg2(uint32_t d_tmem, uint64_t a_desc,
                                                uint64_t b_desc, uint32_t idesc,
                                                uint32_t enable_d) {
    asm volatile(
        "{\n\t"
        ".reg .pred p;\n\t"
        "setp.ne.u32 p, %5, 0;\n\t"
        "tcgen05.mma.cta_group::2.kind::tf32 [%0], %1, %2, %3, "
        "{%4, %4, %4, %4, %4, %4, %4, %4}, p;\n\t"
        "}"
        :: "r"(d_tmem), "l"(a_desc), "l"(b_desc), "r"(idesc), "r"(0u),
           "r"(enable_d)
        : "memory");
}

#define LDTM_X32(r, addr)                                                       \
    asm volatile(                                                               \
        "tcgen05.ld.sync.aligned.32x32b.x32.b32 "                               \
        "{%0, %1, %2, %3, %4, %5, %6, %7, "                                     \
        " %8, %9, %10, %11, %12, %13, %14, %15, "                               \
        " %16, %17, %18, %19, %20, %21, %22, %23, "                             \
        " %24, %25, %26, %27, %28, %29, %30, %31}, [%32];"                      \
        : "=r"((r)[0]),  "=r"((r)[1]),  "=r"((r)[2]),  "=r"((r)[3]),            \
          "=r"((r)[4]),  "=r"((r)[5]),  "=r"((r)[6]),  "=r"((r)[7]),            \
          "=r"((r)[8]),  "=r"((r)[9]),  "=r"((r)[10]), "=r"((r)[11]),           \
          "=r"((r)[12]), "=r"((r)[13]), "=r"((r)[14]), "=r"((r)[15]),           \
          "=r"((r)[16]), "=r"((r)[17]), "=r"((r)[18]), "=r"((r)[19]),           \
          "=r"((r)[20]), "=r"((r)[21]), "=r"((r)[22]), "=r"((r)[23]),           \
          "=r"((r)[24]), "=r"((r)[25]), "=r"((r)[26]), "=r"((r)[27]),           \
          "=r"((r)[28]), "=r"((r)[29]), "=r"((r)[30]), "=r"((r)[31])            \
        : "r"(addr))
#endif  // HAS_TCGEN05

// Warp-cooperative inv-norm of one x row from gmem (coalesced float4).
__device__ __forceinline__ float warp_row_invnorm(const float* __restrict__ x,
                                                  int row, int lane) {
    const float4* xr = (const float4*)(x + (size_t)row * K_DIM);
    float ss = 0.f;
#pragma unroll
    for (int j = 0; j < 16; j++) {
        float4 v = __ldg(&xr[lane + j * 32]);
        ss += v.x * v.x + v.y * v.y + v.z * v.z + v.w * v.w;
    }
#pragma unroll
    for (int o = 16; o > 0; o >>= 1) ss += __shfl_xor_sync(0xffffffffu, ss, o);
    return 1.f / (sqrtf(ss) + 1e-4f);
}

// ---------------------------------------------------------------- GEMM kernel
__global__ __launch_bounds__(THREADS, 1) __cluster_dims__(2, 1, 1)
void ff_gemm_kernel(
    const __grid_constant__ CUtensorMap tma_a,
    const __grid_constant__ CUtensorMap tma_b,
    const float* __restrict__ xg,
    const float* __restrict__ bias,
    float* __restrict__ out)
{
    extern __shared__ char smem[];
    uint32_t sb = smem_u32(smem);
    int tid = threadIdx.x;
    int wid = tid >> 5;
    int lane = tid & 31;

#if HAS_TCGEN05
    // ============= persistent cg2 path: 256x256 cluster tiles ==============
    uint32_t rank = cluster_rank();
    int cid = blockIdx.x >> 1;

    if (tid == 0) {
#pragma unroll
        for (int s = 0; s < STAGES; s++) {
            // leader full: local expect_tx arrive + relay arrive from rank1
            MBARRIER_INIT(sb + OFF_FULL(s), rank == 0 ? 2 : 1);
            MBARRIER_INIT(sb + OFF_EMPTY(s), 1);   // cg2 commit multicast
        }
#pragma unroll
        for (int b2 = 0; b2 < 2; b2++) {
            MBARRIER_INIT(sb + OFF_ACCF(b2), 1);   // cg2 commit multicast
            MBARRIER_INIT(sb + OFF_ACCE(b2), 8);   // 4 epi warps x 2 CTAs (leader)
        }
    }
    if (wid == 5) {
        TCGEN05_ALLOC_CG2(sb + OFF_TMEM, 512);     // 2 x 256-col acc buffers
    }
    __syncthreads();
    CLUSTER_SYNC();   // barriers + TMEM visible before any cluster-scope op

    uint32_t tmem;
    asm volatile("ld.shared.b32 %0, [%1];" : "=r"(tmem) : "r"(sb + OFF_TMEM));

    if (wid == 4) {
        // ---- TMA producer (both ranks): distinct A M-half + B N-half ----
        if (lane == 0) {
            int s = 0, pe = 1;
            for (int t = cid; t < NSUPC; t += NCLUST) {
                int n0 = (t & 7) * BNC + (int)rank * 128;     // B rows (N-half)
                int m0 = (t >> 3) * 256 + (int)rank * 128;    // A rows (M-half)
                for (int k = 0; k < KT; k++) {
                    MBARRIER_WAIT_PARITY(sb + OFF_EMPTY(s), pe);
                    uint32_t st = sb + OFF_DATA + s * STAGE_BYTES;
                    MBARRIER_EXPECT_TX(sb + OFF_FULL(s), STAGE_BYTES);
                    TMA_LOAD_2D(st,           &tma_a, k * BK, m0, sb + OFF_FULL(s));
                    TMA_LOAD_2D(st + A_BYTES, &tma_b, k * BK, n0, sb + OFF_FULL(s));
                    if (++s == STAGES) { s = 0; pe ^= 1; }
                }
            }
        }
    } else if (wid == 5) {
        if (rank == 0) {
            // ---- leader MMA warp: cg2 M=256 N=256 ----
            TCGEN05_FENCE_AFTER();
            if (lane == 0) {
                int s = 0, pf = 0;
                int pae0 = 1, pae1 = 1;
                int ti = 0;
                for (int t = cid; t < NSUPC; t += NCLUST, ti++) {
                    int buf = ti & 1;
                    if (buf) { MBARRIER_WAIT_PARITY(sb + OFF_ACCE(1), pae1); pae1 ^= 1; }
                    else     { MBARRIER_WAIT_PARITY(sb + OFF_ACCE(0), pae0); pae0 ^= 1; }
                    uint32_t dacc = tmem + buf * 256;
                    for (int k = 0; k < KT; k++) {
                        MBARRIER_WAIT_PARITY(sb + OFF_FULL(s), pf);
                        uint32_t st = sb + OFF_DATA + s * STAGE_BYTES;
                        uint64_t ad = make_desc_sw128(st);
                        uint64_t bd = make_desc_sw128(st + A_BYTES);
#pragma unroll
                        for (int sub = 0; sub < 4; sub++) {
                            mma_tf32_ss_cg2(dacc, ad + sub * 2, bd + sub * 2,
                                            IDESC_CG2, (uint32_t)(k | sub));
                        }
                        // stage reusable in BOTH CTAs when these MMAs complete
                        TCGEN05_COMMIT_MC_CG2(sb + OFF_EMPTY(s), 0x3);
                        if (++s == STAGES) { s = 0; pf ^= 1; }
                    }
                    TCGEN05_COMMIT_MC_CG2(sb + OFF_ACCF(buf), 0x3);
                }
            }
        } else {
            // ---- rank1 relay: forward local TMA completions to leader ----
            if (lane == 0) {
                int s = 0, pr = 0;
                for (int t = cid; t < NSUPC; t += NCLUST) {
                    for (int k = 0; k < KT; k++) {
                        MBARRIER_WAIT_PARITY(sb + OFF_FULL(s), pr);
                        MBARRIER_ARRIVE_RANK0(sb + OFF_FULL(s));
                        if (++s == STAGES) { s = 0; pr ^= 1; }
                    }
                }
            }
        }
    } else {
        // ---- epilogue warps 0-3 (both ranks) ----
        // Phase 1 (hidden under first tile's mainloop): this CTA computes
        // inv-norms for its disjoint row range ONCE, then a one-shot grid
        // barrier (all 148 CTAs wave-1 resident; epoch/counter self-resets
        // across CUDA-graph replays).
        {
            unsigned e0 = ld_acquire_gpu(&g_epoch);   // before OUR arrival
            int r0 = blockIdx.x * ROWS_PER_CTA;
            int r1 = r0 + ROWS_PER_CTA;
            if (r1 > B_ROWS) r1 = B_ROWS;
            for (int r = r0 + wid; r < r1; r += 4) {
                float iv = warp_row_invnorm(xg, r, lane);
                if (lane == 0) g_inv_norm[r] = iv;
            }
            asm volatile("bar.sync 1, 128;" ::: "memory");  // 4 epi warps
            if (wid == 0 && lane == 0) {
                __threadfence();                            // release norms
                if (atomicAdd(&g_cnt, 1u) == GRID_P - 1) {
                    g_cnt = 0;                              // reset for replay
                    __threadfence();
                    atomicAdd(&g_epoch, 1u);                // release all
                }
            }
            if (lane == 0) {
                while (ld_acquire_gpu(&g_epoch) == e0) { }
            }
            __syncwarp();
            __threadfence();                                // acquire norms
        }

        int pfa0 = 0, pfa1 = 0;
        int ti = 0;
        for (int t = cid; t < NSUPC; t += NCLUST, ti++) {
            int buf = ti & 1;
            if (buf) { MBARRIER_WAIT_PARITY(sb + OFF_ACCF(1), pfa1); pfa1 ^= 1; }
            else     { MBARRIER_WAIT_PARITY(sb + OFF_ACCF(0), pfa0); pfa0 ^= 1; }
            TCGEN05_FENCE_AFTER();

            int n0 = (t & 7) * BNC;
            int m0 = (t >> 3) * 256 + (int)rank * 128;
            int m = m0 + wid * 32 + lane;
            float inv = g_inv_norm[m];
            float* orow = out + (size_t)m * N_DIM + n0;
            uint32_t tb = tmem + buf * 256;
#pragma unroll
            for (int cb = 0; cb < BNC; cb += 32) {
                uint32_t r[32];
                LDTM_X32(r, tb + cb);
                TCGEN05_WAIT_LD();
#pragma unroll
                for (int i = 0; i < 32; i += 4) {
                    float4 bv = __ldg((const float4*)&bias[n0 + cb + i]);
                    float4 v;
                    v.x = fmaxf(fmaf(__uint_as_float(r[i + 0]), inv, bv.x), 0.f);
                    v.y = fmaxf(fmaf(__uint_as_float(r[i + 1]), inv, bv.y), 0.f);
                    v.z = fmaxf(fmaf(__uint_as_float(r[i + 2]), inv, bv.z), 0.f);
                    v.w = fmaxf(fmaf(__uint_as_float(r[i + 3]), inv, bv.w), 0.f);
                    *(float4*)(orow + cb + i) = v;
                }
            }
            TCGEN05_FENCE_BEFORE();
            __syncwarp();
            if (lane == 0) MBARRIER_ARRIVE_RANK0(sb + OFF_ACCE(buf));
        }
    }
    __syncthreads();
    CLUSTER_SYNC();   // all TMEM reads done in both CTAs before dealloc
    if (wid == 5) {
        TCGEN05_RELINQ_CG2();
        TCGEN05_DEALLOC_CG2(tmem, 512);
    }
    CLUSTER_SYNC();   // no CTA exits while peer ops may target its smem

#else
    // ============ fallback (plain sm_103): persistent mma.sync path ========
#define NTILE_FB ((B_ROWS / BM) * (N_DIM / 128))   // 2048
    int bid = blockIdx.x;
    if (tid == 0) {
#pragma unroll
        for (int s = 0; s < STAGES; s++) {
            MBARRIER_INIT(sb + OFF_FULL(s), 1);
            MBARRIER_INIT(sb + OFF_EMPTY(s), 4);
        }
    }
    __syncthreads();

    if (wid == 4) {
        if (lane == 0) {
            int s = 0, pe = 1;
            for (int t = bid; t < NTILE_FB; t += GRID_P) {
                int n0 = (t & 15) * 128;
                int m0 = (t >> 4) * BM;
                for (int k = 0; k < KT; k++) {
                    MBARRIER_WAIT_PARITY(sb + OFF_EMPTY(s), pe);
                    uint32_t st = sb + OFF_DATA + s * STAGE_BYTES;
                    MBARRIER_EXPECT_TX(sb + OFF_FULL(s), 32768);
                    TMA_LOAD_2D(st,           &tma_a, k * BK, m0, sb + OFF_FULL(s));
                    TMA_LOAD_2D(st + A_BYTES, &tma_b, k * BK, n0, sb + OFF_FULL(s));
                    if (++s == STAGES) { s = 0; pe ^= 1; }
                }
            }
        }
    } else if (wid < 4) {
        int wm = wid >> 1, wn = wid & 1;
        const int xorpat = (lane & 7) << 4;
        const int a_row  = wm * 64 + (lane & 15);
        const int a_colb = (lane >> 4) * 16;
        const int b_row  = wn * 64 + (lane & 7) + ((lane >> 4) * 8);
        const int b_colb = ((lane >> 3) & 1) * 16;
        float* ninv = (float*)(smem + OFF_NORM);   // 128 floats per tile

        int s = 0, pf = 0;
        for (int t = bid; t < NTILE_FB; t += GRID_P) {
            int n0 = (t & 15) * 128;
            int m0 = (t >> 4) * BM;

            {
                int rb = m0 + wid * 32;
                for (int r = 0; r < 32; r++) {
                    float iv = warp_row_invnorm(xg, rb + r, lane);
                    if (lane == 0) ninv[wid * 32 + r] = iv;
                }
            }
            asm volatile("bar.sync 1, 128;" ::: "memory");

            float c[4][8][4];
#pragma unroll
            for (int a1 = 0; a1 < 4; a1++)
#pragma unroll
                for (int a2 = 0; a2 < 8; a2++)
#pragma unroll
                    for (int a3 = 0; a3 < 4; a3++) c[a1][a2][a3] = 0.f;

            for (int k = 0; k < KT; k++) {
                MBARRIER_WAIT_PARITY(sb + OFF_FULL(s), pf);
                uint32_t sa  = sb + OFF_DATA + s * STAGE_BYTES;
                uint32_t sbm = sa + A_BYTES;
#pragma unroll
                for (int q = 0; q < 4; q++) {
                    uint32_t a[4][4], bf[4][4];
#pragma unroll
                    for (int mt = 0; mt < 4; mt++) {
                        uint32_t addr = sa + (uint32_t)((a_row + mt * 16) * 128 +
                                         ((q * 32 + a_colb) ^ xorpat));
                        LDSM_X4(a[mt], addr);
                    }
#pragma unroll
                    for (int p = 0; p < 4; p++) {
                        uint32_t addr = sbm + (uint32_t)((b_row + p * 16) * 128 +
                                         ((q * 32 + b_colb) ^ xorpat));
                        LDSM_X4(bf[p], addr);
                    }
#pragma unroll
                    for (int mt = 0; mt < 4; mt++)
#pragma unroll
                        for (int nt = 0; nt < 8; nt++) {
                            const uint32_t* bb = &bf[nt >> 1][(nt & 1) * 2];
                            MMA_TF32(c[mt][nt], a[mt], bb[0], bb[1]);
                        }
                }
                __syncwarp();
                if (lane == 0) MBARRIER_ARRIVE(sb + OFF_EMPTY(s));
                if (++s == STAGES) { s = 0; pf ^= 1; }
            }

            int g = lane >> 2, tt = lane & 3;
#pragma unroll
            for (int mt = 0; mt < 4; mt++) {
                int r0 = m0 + wm * 64 + mt * 16 + g;
                float inv0 = ninv[r0 - m0];
                float inv1 = ninv[r0 - m0 + 8];
                float* p0 = out + (size_t)r0 * N_DIM + n0;
                float* p1 = out + (size_t)(r0 + 8) * N_DIM + n0;
#pragma unroll
                for (int nt = 0; nt < 8; nt++) {
                    int cl = wn * 64 + nt * 8 + 2 * tt;
                    float b0 = __ldg(&bias[n0 + cl]), b1 = __ldg(&bias[n0 + cl + 1]);
                    float2 v0, v1;
                    v0.x = fmaxf(fmaf(c[mt][nt][0], inv0, b0), 0.f);
                    v0.y = fmaxf(fmaf(c[mt][nt][1], inv0, b1), 0.f);
                    v1.x = fmaxf(fmaf(c[mt][nt][2], inv1, b0), 0.f);
                    v1.y = fmaxf(fmaf(c[mt][nt][3], inv1, b1), 0.f);
                    *(float2*)(p0 + cl) = v0;
                    *(float2*)(p1 + cl) = v1;
                }
            }
            asm volatile("bar.sync 1, 128;" ::: "memory");
        }
    }
#endif
}

// ---------------------------------------------------------------- host side
typedef CUresult (*PFN_encodeTiled)(
    CUtensorMap*, CUtensorMapDataType, cuuint32_t, void*,
    const cuuint64_t*, const cuuint64_t*, const cuuint32_t*, const cuuint32_t*,
    CUtensorMapInterleave, CUtensorMapSwizzle, CUtensorMapL2promotion,
    CUtensorMapFloatOOBfill);

static PFN_encodeTiled get_encoder() {
    void* p = nullptr;
    cudaDriverEntryPointQueryResult st;
    cudaGetDriverEntryPointByVersion("cuTensorMapEncodeTiled", &p, 12000,
                                     cudaEnableDefault, &st);
    return (PFN_encodeTiled)p;
}

static void make_map(PFN_encodeTiled enc, CUtensorMap* map, const void* base,
                     uint64_t rows) {
    cuuint64_t dims[2]    = {(cuuint64_t)K_DIM, (cuuint64_t)rows};
    cuuint64_t strides[1] = {(cuuint64_t)K_DIM * sizeof(float)};
    cuuint32_t box[2]     = {(cuuint32_t)BK, (cuuint32_t)BM};
    cuuint32_t es[2]      = {1, 1};
    enc(map, CU_TENSOR_MAP_DATA_TYPE_FLOAT32, 2, (void*)base,
        dims, strides, box, es,
        CU_TENSOR_MAP_INTERLEAVE_NONE, CU_TENSOR_MAP_SWIZZLE_128B,
        CU_TENSOR_MAP_L2_PROMOTION_L2_128B, CU_TENSOR_MAP_FLOAT_OOB_FILL_NONE);
}

extern "C" void kernel_launch(void* const* d_in, const int* in_sizes, int n_in,
                              void* d_out, int out_size) {
    const float* x = (const float*)d_in[0];
    const float* W = (const float*)d_in[1];
    const float* b = (const float*)d_in[2];
    float* out = (float*)d_out;

    cudaFuncSetAttribute(ff_gemm_kernel,
                         cudaFuncAttributeMaxDynamicSharedMemorySize, SMEM_TOTAL);

    PFN_encodeTiled enc = get_encoder();
    CUtensorMap mapA, mapB;
    make_map(enc, &mapA, x, B_ROWS);
    make_map(enc, &mapB, W, N_DIM);

    ff_gemm_kernel<<<GRID_P, THREADS, SMEM_TOTAL>>>(mapA, mapB, x, b, out);
}